// round 8
// baseline (speedup 1.0000x reference)
#include <cuda_runtime.h>
#include <cuda_fp16.h>
#include <cstdint>

// Problem constants
#define Hh   16
#define Dd   64
#define Ee   1024
#define NBa  4
#define TBq  1024
#define TWq  512
#define NHh  64      // NBa*Hh
#define Rr   33      // 2L+1
#define Ll   16
#define SCALE 0.125f // D^-0.5

// ---------------- scratch (device globals; no allocation) ----------------
__device__ float g_q_bpe[NHh * TBq * Dd];
__device__ float g_k_bpe[NHh * TBq * Dd];
__device__ float g_vT   [NHh * 128 * TBq];   // v transposed [z][d][t], rows 64..127 stay 0
__device__ float g_q_w  [NHh * TWq * Dd];
__device__ float g_k_w  [NHh * TWq * Dd];
__device__ float g_attn [NHh * TBq * TBq];
__device__ float g_awT  [NHh * TWq * TWq];   // word logits transposed [s',w]
__device__ float g_tmp  [NHh * TBq * TWq];
__device__ float g_arb  [NHh * TBq * Rr];
__device__ float g_arw  [NHh * TWq * Rr];
__device__ float g_x2   [TBq * NBa * Ee];

// ============ fp16 3-term (Markidis) mma.sync GEMM core ============
// C = (A*sA) * (B*sB)^T / (sA*sB). A:[M,K] (lda), B:[N,K] (ldb), fp32 gmem.
// Tile 128x128, BK=16, 256 threads, warp grid 2x4, warp tile 64x32.
// SMEM (b32 units): per buffer AH[128*12] AL BH BL = 6144; double buffered.
#define SROW 12                       // b32 per staged row (16 halves + pad)
#define MOFF 1536                     // 128*SROW
#define BUFW 6144                     // 4 matrices
#define MM_SMEM (2 * BUFW * 4)        // bytes = 49152

__device__ __forceinline__ void ptx_mma_h(float* c, const uint32_t* a, const uint32_t* b) {
    asm volatile(
        "mma.sync.aligned.m16n8k16.row.col.f32.f16.f16.f32 "
        "{%0,%1,%2,%3},{%4,%5,%6,%7},{%8,%9},{%0,%1,%2,%3};"
        : "+f"(c[0]), "+f"(c[1]), "+f"(c[2]), "+f"(c[3])
        : "r"(a[0]), "r"(a[1]), "r"(a[2]), "r"(a[3]), "r"(b[0]), "r"(b[1]));
}

__device__ __forceinline__ uint32_t h2pack(float x0, float x1, float s, uint32_t& lo) {
    float a = x0 * s, b = x1 * s;
    __half ha = __float2half_rn(a), hb = __float2half_rn(b);
    __half la = __float2half_rn(a - __half2float(ha));
    __half lb = __float2half_rn(b - __half2float(hb));
    __half2 h = __halves2half2(ha, hb), l = __halves2half2(la, lb);
    lo = *(uint32_t*)&l;
    return *(uint32_t*)&h;
}

// stage one float4 (4 K-values) of one row into hi/lo matrices
__device__ __forceinline__ void stage(uint32_t* mh, int r, int fkq, float4 v, float s) {
    uint32_t l0, l1;
    uint32_t h0 = h2pack(v.x, v.y, s, l0);
    uint32_t h1 = h2pack(v.z, v.w, s, l1);
    *(uint2*)(mh + r * SROW + fkq)        = make_uint2(h0, h1);
    *(uint2*)(mh + MOFF + r * SROW + fkq) = make_uint2(l0, l1);
}

// acc[mf=4][nf=4][4]
__device__ __forceinline__ void mm_core_h(
    const float* __restrict__ A, const float* __restrict__ B,
    int lda, int ldb, int K, float sA, float sB,
    float acc[4][4][4], uint32_t* sm)
{
    const int tid = threadIdx.x, lane = tid & 31, wid = tid >> 5;
    const int wm = wid >> 2, wn = wid & 3, lr = lane >> 2, lc = lane & 3;
    const int fr  = tid >> 2;             // 0..63
    const int fkq = (tid & 3) << 1;       // b32 col: 0,2,4,6
    const int fk  = fkq << 1;             // fp32 col: 0,4,8,12

    float4 fa0, fa1, fb0, fb1;
    fa0 = *(const float4*)(A + (size_t)fr * lda + fk);
    fa1 = *(const float4*)(A + (size_t)(fr + 64) * lda + fk);
    fb0 = *(const float4*)(B + (size_t)fr * ldb + fk);
    fb1 = *(const float4*)(B + (size_t)(fr + 64) * ldb + fk);
    stage(sm,        fr,      fkq, fa0, sA);
    stage(sm,        fr + 64, fkq, fa1, sA);
    stage(sm + 2 * MOFF, fr,      fkq, fb0, sB);
    stage(sm + 2 * MOFF, fr + 64, fkq, fb1, sB);
    __syncthreads();

    const int NIT = K >> 4;
    for (int it = 0; it < NIT; it++) {
        if (it + 1 < NIT) {
            const int k0 = (it + 1) << 4;
            fa0 = *(const float4*)(A + (size_t)fr * lda + k0 + fk);
            fa1 = *(const float4*)(A + (size_t)(fr + 64) * lda + k0 + fk);
            fb0 = *(const float4*)(B + (size_t)fr * ldb + k0 + fk);
            fb1 = *(const float4*)(B + (size_t)(fr + 64) * ldb + k0 + fk);
        }
        const uint32_t* s  = sm + (it & 1) * BUFW;
        const uint32_t* AH = s;
        const uint32_t* AL = s + MOFF;
        const uint32_t* BH = s + 2 * MOFF;
        const uint32_t* BL = s + 3 * MOFF;

        uint32_t ah[4][4], al[4][4], bh[4][2], bl[4][2];
        #pragma unroll
        for (int mf = 0; mf < 4; mf++) {
            const int rb = wm * 64 + mf * 16 + lr;
            ah[mf][0] = AH[rb * SROW + lc];
            ah[mf][1] = AH[(rb + 8) * SROW + lc];
            ah[mf][2] = AH[rb * SROW + lc + 4];
            ah[mf][3] = AH[(rb + 8) * SROW + lc + 4];
            al[mf][0] = AL[rb * SROW + lc];
            al[mf][1] = AL[(rb + 8) * SROW + lc];
            al[mf][2] = AL[rb * SROW + lc + 4];
            al[mf][3] = AL[(rb + 8) * SROW + lc + 4];
        }
        #pragma unroll
        for (int nf = 0; nf < 4; nf++) {
            const int nb = wn * 32 + nf * 8 + lr;
            bh[nf][0] = BH[nb * SROW + lc];
            bh[nf][1] = BH[nb * SROW + lc + 4];
            bl[nf][0] = BL[nb * SROW + lc];
            bl[nf][1] = BL[nb * SROW + lc + 4];
        }
        #pragma unroll
        for (int term = 0; term < 3; term++) {
            #pragma unroll
            for (int mf = 0; mf < 4; mf++)
                #pragma unroll
                for (int nf = 0; nf < 4; nf++) {
                    const uint32_t* ap = (term == 2) ? al[mf] : ah[mf];
                    const uint32_t* bp = (term == 1) ? bl[nf] : bh[nf];
                    ptx_mma_h(acc[mf][nf], ap, bp);
                }
        }
        if (it + 1 < NIT) {
            uint32_t* d = sm + ((it + 1) & 1) * BUFW;
            stage(d,            fr,      fkq, fa0, sA);
            stage(d,            fr + 64, fkq, fa1, sA);
            stage(d + 2 * MOFF, fr,      fkq, fb0, sB);
            stage(d + 2 * MOFF, fr + 64, fkq, fb1, sB);
            __syncthreads();
        }
    }
}

// epilogue iteration helper (256-thread, warp tile 64x32)
#define EPI_BEGIN \
    const int lane_ = threadIdx.x & 31, wid_ = threadIdx.x >> 5; \
    const int wm_ = wid_ >> 2, wn_ = wid_ & 3, lr_ = lane_ >> 2, lc_ = lane_ & 3; \
    _Pragma("unroll") for (int mf = 0; mf < 4; mf++) \
    _Pragma("unroll") for (int nf = 0; nf < 4; nf++) \
    _Pragma("unroll") for (int hf = 0; hf < 2; hf++) { \
        const int r  = wm_ * 64 + mf * 16 + lr_ + hf * 8; \
        const int cI = wn_ * 32 + nf * 8 + lc_ * 2; \
        const float v0 = acc[mf][nf][hf * 2], v1 = acc[mf][nf][hf * 2 + 1];
#define EPI_END }

// ---------------- mma-based kernels ----------------

// projection + bias + scale; vmode=0: heads layout; vmode=1: vT layout [z][d][t]
__global__ void __launch_bounds__(256, 1) k_proj_mma(
    const float* __restrict__ X, const float* __restrict__ W,
    const float* __restrict__ bias, float* __restrict__ out, int T, float scale,
    int vmode, float sA, float sB, float inv)
{
    extern __shared__ uint32_t sm[];
    float acc[4][4][4] = {};
    const int row0 = blockIdx.y * 128, col0 = blockIdx.x * 128;
    mm_core_h(X + (size_t)row0 * Ee, W + (size_t)col0 * Ee, Ee, Ee, Ee, sA, sB, acc, sm);
    EPI_BEGIN
        const int gr = row0 + r, gc = col0 + cI;
        const int t = gr >> 2, bb = gr & 3;
        const int h = gc >> 6, d = gc & 63;
        const int z = bb * Hh + h;
        const float o0 = (v0 * inv + bias[gc]) * scale;
        const float o1 = (v1 * inv + bias[gc + 1]) * scale;
        if (vmode) {
            out[((size_t)z * 128 + d) * TBq + t]     = o0;
            out[((size_t)z * 128 + d + 1) * TBq + t] = o1;
        } else {
            *(float2*)&out[(((size_t)z) * T + t) * Dd + d] = make_float2(o0, o1);
        }
    EPI_END
}

// QK^T + relative logits.
// mode 0: A=q, B=k, out[t][s]; mode 1: A=k, B=q, out[s][t] (transposed logits)
__global__ void __launch_bounds__(256, 1) k_attn_mma(
    const float* __restrict__ Amat, const float* __restrict__ Bmat,
    const float* __restrict__ allr, float* __restrict__ attn, int T, int mode,
    float sA, float sB, float inv)
{
    extern __shared__ uint32_t sm[];
    const int z = blockIdx.z;
    const int row0 = blockIdx.y * 128, col0 = blockIdx.x * 128;
    const float* A = Amat + (size_t)z * T * Dd + (size_t)row0 * Dd;
    const float* B = Bmat + (size_t)z * T * Dd + (size_t)col0 * Dd;
    float acc[4][4][4] = {};
    mm_core_h(A, B, Dd, Dd, Dd, sA, sB, acc, sm);
    EPI_BEGIN
        const int gr = row0 + r;
        const int gc = col0 + cI;
        float o0, o1;
        if (mode == 0) {
            const float* ar = allr + ((size_t)z * T + gr) * Rr;
            int r0c = gc - gr;     r0c = r0c < -Ll ? -Ll : (r0c > Ll ? Ll : r0c);
            int r1c = gc + 1 - gr; r1c = r1c < -Ll ? -Ll : (r1c > Ll ? Ll : r1c);
            o0 = v0 * inv + ar[r0c + Ll];
            o1 = v1 * inv + ar[r1c + Ll];
        } else {
            int r0c = gr - gc;       r0c = r0c < -Ll ? -Ll : (r0c > Ll ? Ll : r0c);
            int r1c = gr - (gc + 1); r1c = r1c < -Ll ? -Ll : (r1c > Ll ? Ll : r1c);
            o0 = v0 * inv + allr[((size_t)z * T + gc) * Rr + r0c + Ll];
            o1 = v1 * inv + allr[((size_t)z * T + gc + 1) * Rr + r1c + Ll];
        }
        *(float2*)&attn[((size_t)z * T + gr) * T + gc] = make_float2(o0, o1);
    EPI_END
}

// batched NT GEMM: C[z] (+)= A[z/aZd] * B[z/bZd]^T
template<bool ADD>
__global__ void __launch_bounds__(256, 1) k_mmNT(
    const float* __restrict__ Ab, const float* __restrict__ Bb, float* __restrict__ Cb,
    int lda, int ldb, int ldc, int K,
    long long aZs, int aZd, long long bZs, int bZd, long long cZs,
    float sA, float sB, float inv)
{
    extern __shared__ uint32_t sm[];
    const int z = blockIdx.z;
    const int row0 = blockIdx.y * 128, col0 = blockIdx.x * 128;
    const float* A = Ab + (size_t)(z / aZd) * aZs + (size_t)row0 * lda;
    const float* B = Bb + (size_t)(z / bZd) * bZs + (size_t)col0 * ldb;
    float* C = Cb + (size_t)z * cZs;
    float acc[4][4][4] = {};
    mm_core_h(A, B, lda, ldb, K, sA, sB, acc, sm);
    EPI_BEGIN
        float2* p = (float2*)&C[(size_t)(row0 + r) * ldc + col0 + cI];
        float2 v = make_float2(v0 * inv, v1 * inv);
        if (ADD) { float2 o = *p; v.x += o.x; v.y += o.y; }
        *p = v;
    EPI_END
}

// probs @ v via vT (padded to 128 rows; pad rows are zero): columns >= 64 discarded
__global__ void __launch_bounds__(256, 1) k_pv_mma(float sA, float sB, float inv)
{
    extern __shared__ uint32_t sm[];
    const int z = blockIdx.z, bb = z / Hh, h = z % Hh;
    const int row0 = blockIdx.y * 128;
    const float* A = g_attn + (size_t)z * TBq * TBq + (size_t)row0 * TBq;
    const float* B = g_vT   + (size_t)z * 128 * TBq;
    float acc[4][4][4] = {};
    mm_core_h(A, B, TBq, TBq, TBq, sA, sB, acc, sm);
    EPI_BEGIN
        if (cI < 64) {
            const int t = row0 + r, d = cI;
            *(float2*)&g_x2[((size_t)t * NBa + bb) * Ee + h * Dd + d] =
                make_float2(v0 * inv, v1 * inv);
        }
    EPI_END
}

// output projection + bias
__global__ void __launch_bounds__(256, 1) k_final_mma(
    const float* __restrict__ X, const float* __restrict__ Wo,
    const float* __restrict__ bo, float* __restrict__ out,
    float sA, float sB, float inv)
{
    extern __shared__ uint32_t sm[];
    float acc[4][4][4] = {};
    const int row0 = blockIdx.y * 128, col0 = blockIdx.x * 128;
    mm_core_h(X + (size_t)row0 * Ee, Wo + (size_t)col0 * Ee, Ee, Ee, Ee, sA, sB, acc, sm);
    EPI_BEGIN
        const int gr = row0 + r, gc = col0 + cI;
        *(float2*)&out[(size_t)gr * Ee + gc] =
            make_float2(v0 * inv + bo[gc], v1 * inv + bo[gc + 1]);
    EPI_END
}

// ---------------- remaining SIMT kernels ----------------
__global__ void k_allr(const float* __restrict__ q, const float* __restrict__ table,
                       float* __restrict__ allr, int T)
{
    int idx = blockIdx.x * blockDim.x + threadIdx.x;
    if (idx >= NHh * T * Rr) return;
    int r   = idx % Rr;
    int row = idx / Rr;
    const float* qp = q + (size_t)row * Dd;
    const float* tp = table + r * Dd;
    float s = 0.f;
    #pragma unroll
    for (int d = 0; d < Dd; d++) s += qp[d] * tp[d];
    allr[idx] = s;
}

__global__ void k_softmax()
{
    const size_t row = blockIdx.x;
    float4* p = (float4*)(g_attn + row * TBq);
    float4 v = p[threadIdx.x];
    float m = fmaxf(fmaxf(v.x, v.y), fmaxf(v.z, v.w));

    __shared__ float smx[8];
    __shared__ float ssm[8];
    int lane = threadIdx.x & 31, w = threadIdx.x >> 5;
    #pragma unroll
    for (int o = 16; o; o >>= 1) m = fmaxf(m, __shfl_xor_sync(0xffffffffu, m, o));
    if (!lane) smx[w] = m;
    __syncthreads();
    m = smx[0];
    #pragma unroll
    for (int i = 1; i < 8; i++) m = fmaxf(m, smx[i]);

    v.x = expf(v.x - m); v.y = expf(v.y - m);
    v.z = expf(v.z - m); v.w = expf(v.w - m);
    float s = v.x + v.y + v.z + v.w;
    #pragma unroll
    for (int o = 16; o; o >>= 1) s += __shfl_xor_sync(0xffffffffu, s, o);
    if (!lane) ssm[w] = s;
    __syncthreads();
    s = 0.f;
    #pragma unroll
    for (int i = 0; i < 8; i++) s += ssm[i];

    float inv = 1.f / s;
    v.x *= inv; v.y *= inv; v.z *= inv; v.w *= inv;
    p[threadIdx.x] = v;
}

// ---------------- launcher ----------------
extern "C" void kernel_launch(void* const* d_in, const int* in_sizes, int n_in,
                              void* d_out, int out_size)
{
    const float* query_bpe  = (const float*)d_in[0];
    const float* query_word = (const float*)d_in[1];
    const float* mapping    = (const float*)d_in[2];
    const float* Wq_bpe     = (const float*)d_in[3];
    const float* bq_bpe     = (const float*)d_in[4];
    const float* Wk_bpe     = (const float*)d_in[5];
    const float* bk_bpe     = (const float*)d_in[6];
    const float* Wq_word    = (const float*)d_in[7];
    const float* bq_word    = (const float*)d_in[8];
    const float* Wk_word    = (const float*)d_in[9];
    const float* bk_word    = (const float*)d_in[10];
    const float* Wv         = (const float*)d_in[11];
    const float* bv         = (const float*)d_in[12];
    const float* Wo         = (const float*)d_in[13];
    const float* bo         = (const float*)d_in[14];
    const float* rel_keys   = (const float*)d_in[15];
    float* out = (float*)d_out;

    float *q_bpe, *k_bpe, *vT, *q_w, *k_w, *attn, *awT, *tmp, *arb, *arw, *x2;
    cudaGetSymbolAddress((void**)&q_bpe, g_q_bpe);
    cudaGetSymbolAddress((void**)&k_bpe, g_k_bpe);
    cudaGetSymbolAddress((void**)&vT,    g_vT);
    cudaGetSymbolAddress((void**)&q_w,   g_q_w);
    cudaGetSymbolAddress((void**)&k_w,   g_k_w);
    cudaGetSymbolAddress((void**)&attn,  g_attn);
    cudaGetSymbolAddress((void**)&awT,   g_awT);
    cudaGetSymbolAddress((void**)&tmp,   g_tmp);
    cudaGetSymbolAddress((void**)&arb,   g_arb);
    cudaGetSymbolAddress((void**)&arw,   g_arw);
    cudaGetSymbolAddress((void**)&x2,    g_x2);

    cudaFuncSetAttribute(k_proj_mma,    cudaFuncAttributeMaxDynamicSharedMemorySize, MM_SMEM);
    cudaFuncSetAttribute(k_attn_mma,    cudaFuncAttributeMaxDynamicSharedMemorySize, MM_SMEM);
    cudaFuncSetAttribute(k_mmNT<false>, cudaFuncAttributeMaxDynamicSharedMemorySize, MM_SMEM);
    cudaFuncSetAttribute(k_mmNT<true>,  cudaFuncAttributeMaxDynamicSharedMemorySize, MM_SMEM);
    cudaFuncSetAttribute(k_pv_mma,      cudaFuncAttributeMaxDynamicSharedMemorySize, MM_SMEM);
    cudaFuncSetAttribute(k_final_mma,   cudaFuncAttributeMaxDynamicSharedMemorySize, MM_SMEM);

    // per-GEMM fp16 prescales (powers of 2, generous overflow margins)
    const float sX = 64.f,    sW = 2048.f,  iXW = 1.f / (sX * sW);     // projections
    const float sQ = 1024.f,  sK = 128.f,   iQK = 1.f / (sQ * sK);     // attn logits
    const float sM = 64.f,    sAw = 128.f,  iMA = 1.f / (sM * sAw);    // tmp = M @ aw^T
    const float sTm = 16.f,   sM2 = 64.f,   iTM = 1.f / (sTm * sM2);   // fuse = tmp @ M^T
    const float sP = 256.f,   sV = 128.f,   iPV = 1.f / (sP * sV);     // probs @ v
    const float sX2 = 128.f,  sWo = 2048.f, iXO = 1.f / (sX2 * sWo);   // final

    // projections (M = T*NB rows); v written transposed+padded
    k_proj_mma<<<dim3(8, 32), 256, MM_SMEM>>>(query_bpe,  Wq_bpe,  bq_bpe,  q_bpe, TBq, SCALE, 0, sX, sW, iXW);
    k_proj_mma<<<dim3(8, 32), 256, MM_SMEM>>>(query_bpe,  Wk_bpe,  bk_bpe,  k_bpe, TBq, 1.0f,  0, sX, sW, iXW);
    k_proj_mma<<<dim3(8, 32), 256, MM_SMEM>>>(query_bpe,  Wv,      bv,      vT,    TBq, 1.0f,  1, sX, sW, iXW);
    k_proj_mma<<<dim3(8, 16), 256, MM_SMEM>>>(query_word, Wq_word, bq_word, q_w,   TWq, SCALE, 0, sX, sW, iXW);
    k_proj_mma<<<dim3(8, 16), 256, MM_SMEM>>>(query_word, Wk_word, bk_word, k_w,   TWq, 1.0f,  0, sX, sW, iXW);

    // relative logit tables
    k_allr<<<(NHh * TBq * Rr + 255) / 256, 256>>>(q_bpe, rel_keys, arb, TBq);
    k_allr<<<(NHh * TWq * Rr + 255) / 256, 256>>>(q_w,   rel_keys, arw, TWq);

    // content + relative logits; word stream computed directly transposed
    k_attn_mma<<<dim3(8, 8, NHh), 256, MM_SMEM>>>(q_bpe, k_bpe, arb, attn, TBq, 0, sQ, sK, iQK);
    k_attn_mma<<<dim3(4, 4, NHh), 256, MM_SMEM>>>(k_w,   q_w,   arw, awT,  TWq, 1, sK, sQ, iQK);

    // fusion chain on tensor cores
    k_mmNT<false><<<dim3(TWq / 128, TBq / 128, NHh), 256, MM_SMEM>>>(
        mapping, awT, tmp, TWq, TWq, TWq, TWq,
        (long long)TBq * TWq, Hh, (long long)TWq * TWq, 1, (long long)TBq * TWq,
        sM, sAw, iMA);
    k_mmNT<true><<<dim3(TBq / 128, TBq / 128, NHh), 256, MM_SMEM>>>(
        tmp, mapping, attn, TWq, TWq, TBq, TWq,
        (long long)TBq * TWq, 1, (long long)TBq * TWq, Hh, (long long)TBq * TBq,
        sTm, sM2, iTM);

    // softmax rows
    k_softmax<<<NHh * TBq, 256>>>();

    // probs @ v on tensor cores
    k_pv_mma<<<dim3(1, 8, NHh), 256, MM_SMEM>>>(sP, sV, iPV);

    // output projection
    k_final_mma<<<dim3(8, 32), 256, MM_SMEM>>>(x2, Wo, bo, out, sX2, sWo, iXO);
}

// round 9
// speedup vs baseline: 1.0834x; 1.0834x over previous
#include <cuda_runtime.h>
#include <cuda_fp16.h>
#include <cstdint>

// Problem constants
#define Hh   16
#define Dd   64
#define Ee   1024
#define NBa  4
#define TBq  1024
#define TWq  512
#define NHh  64      // NBa*Hh
#define Rr   33      // 2L+1
#define Ll   16
#define SCALE 0.125f // D^-0.5

// ---------------- scratch (device globals; no allocation) ----------------
__device__ float g_q_bpe[NHh * TBq * Dd];
__device__ float g_k_bpe[NHh * TBq * Dd];
__device__ float g_vT   [NHh * 128 * TBq];   // v transposed [z][d][t], rows 64..127 stay 0
__device__ float g_q_w  [NHh * TWq * Dd];
__device__ float g_k_w  [NHh * TWq * Dd];
__device__ float g_attn [NHh * TBq * TBq];
__device__ float g_awT  [NHh * TWq * TWq];   // word logits transposed [s',w]
__device__ float g_tmp  [NHh * TBq * TWq];
__device__ float g_arb  [NHh * TBq * Rr];
__device__ float g_arw  [NHh * TWq * Rr];
__device__ float g_x2   [TBq * NBa * Ee];

// ============ fp16 3-term (Markidis) mma.sync GEMM core ============
// C = (A*sA) * (B*sB)^T / (sA*sB). A:[M,K] (lda), B:[N,K] (ldb), fp32 gmem.
// Tile 128x128, BK=16, 256 threads, warp grid 2x4, warp tile 64x32.
// Fragments loaded via ldmatrix.x4 (12 LDSM per K16 per warp vs 48 LDS).
#define SROW 12                       // b32 per staged row (16 halves + pad)
#define MOFF 1536                     // 128*SROW
#define BUFW 6144                     // 4 matrices
#define MM_SMEM (2 * BUFW * 4)        // bytes = 49152

__device__ __forceinline__ void ptx_mma_h(float* c, const uint32_t* a, const uint32_t* b) {
    asm volatile(
        "mma.sync.aligned.m16n8k16.row.col.f32.f16.f16.f32 "
        "{%0,%1,%2,%3},{%4,%5,%6,%7},{%8,%9},{%0,%1,%2,%3};"
        : "+f"(c[0]), "+f"(c[1]), "+f"(c[2]), "+f"(c[3])
        : "r"(a[0]), "r"(a[1]), "r"(a[2]), "r"(a[3]), "r"(b[0]), "r"(b[1]));
}

__device__ __forceinline__ void ldsm4(uint32_t* r, uint32_t saddr) {
    asm volatile("ldmatrix.sync.aligned.m8n8.x4.shared.b16 {%0,%1,%2,%3}, [%4];"
                 : "=r"(r[0]), "=r"(r[1]), "=r"(r[2]), "=r"(r[3]) : "r"(saddr));
}

__device__ __forceinline__ uint32_t h2pack(float x0, float x1, float s, uint32_t& lo) {
    float a = x0 * s, b = x1 * s;
    __half ha = __float2half_rn(a), hb = __float2half_rn(b);
    __half la = __float2half_rn(a - __half2float(ha));
    __half lb = __float2half_rn(b - __half2float(hb));
    __half2 h = __halves2half2(ha, hb), l = __halves2half2(la, lb);
    lo = *(uint32_t*)&l;
    return *(uint32_t*)&h;
}

// stage one float4 (4 K-values) of one row into hi/lo matrices
__device__ __forceinline__ void stage(uint32_t* mh, int r, int fkq, float4 v, float s) {
    uint32_t l0, l1;
    uint32_t h0 = h2pack(v.x, v.y, s, l0);
    uint32_t h1 = h2pack(v.z, v.w, s, l1);
    *(uint2*)(mh + r * SROW + fkq)        = make_uint2(h0, h1);
    *(uint2*)(mh + MOFF + r * SROW + fkq) = make_uint2(l0, l1);
}

// acc[mf=4][nf=4][4]
__device__ __forceinline__ void mm_core_h(
    const float* __restrict__ A, const float* __restrict__ B,
    int lda, int ldb, int K, float sA, float sB,
    float acc[4][4][4], uint32_t* sm)
{
    const int tid = threadIdx.x, lane = tid & 31, wid = tid >> 5;
    const int wm = wid >> 2, wn = wid & 3;
    const int fr  = tid >> 2;             // 0..63
    const int fkq = (tid & 3) << 1;       // b32 col: 0,2,4,6
    const int fk  = fkq << 1;             // fp32 col: 0,4,8,12

    // per-thread ldmatrix addresses (byte offsets within a buffer)
    const uint32_t sbase = (uint32_t)__cvta_generic_to_shared(sm);
    const int q = lane >> 3, rowin = lane & 7;
    uint32_t aoff[4], boff[2];
    #pragma unroll
    for (int mf = 0; mf < 4; mf++)
        aoff[mf] = ((wm * 64 + mf * 16 + (q & 1) * 8 + rowin) * SROW + (q >> 1) * 4) * 4;
    #pragma unroll
    for (int p = 0; p < 2; p++)
        boff[p] = ((wn * 32 + p * 16 + (q >> 1) * 8 + rowin) * SROW + (q & 1) * 4) * 4
                  + 2 * MOFF * 4;

    float4 fa0, fa1, fb0, fb1;
    fa0 = *(const float4*)(A + (size_t)fr * lda + fk);
    fa1 = *(const float4*)(A + (size_t)(fr + 64) * lda + fk);
    fb0 = *(const float4*)(B + (size_t)fr * ldb + fk);
    fb1 = *(const float4*)(B + (size_t)(fr + 64) * ldb + fk);
    stage(sm,            fr,      fkq, fa0, sA);
    stage(sm,            fr + 64, fkq, fa1, sA);
    stage(sm + 2 * MOFF, fr,      fkq, fb0, sB);
    stage(sm + 2 * MOFF, fr + 64, fkq, fb1, sB);
    __syncthreads();

    const int NIT = K >> 4;
    for (int it = 0; it < NIT; it++) {
        if (it + 1 < NIT) {
            const int k0 = (it + 1) << 4;
            fa0 = *(const float4*)(A + (size_t)fr * lda + k0 + fk);
            fa1 = *(const float4*)(A + (size_t)(fr + 64) * lda + k0 + fk);
            fb0 = *(const float4*)(B + (size_t)fr * ldb + k0 + fk);
            fb1 = *(const float4*)(B + (size_t)(fr + 64) * ldb + k0 + fk);
        }
        const uint32_t bufb = sbase + (uint32_t)((it & 1) * BUFW * 4);

        uint32_t ah[4][4], al[4][4], bh[4][2], bl[4][2];
        #pragma unroll
        for (int mf = 0; mf < 4; mf++) {
            ldsm4(ah[mf], bufb + aoff[mf]);
            ldsm4(al[mf], bufb + aoff[mf] + MOFF * 4);
        }
        #pragma unroll
        for (int p = 0; p < 2; p++) {
            uint32_t rb[4], rl[4];
            ldsm4(rb, bufb + boff[p]);
            ldsm4(rl, bufb + boff[p] + MOFF * 4);
            bh[2 * p][0] = rb[0]; bh[2 * p][1] = rb[1];
            bh[2 * p + 1][0] = rb[2]; bh[2 * p + 1][1] = rb[3];
            bl[2 * p][0] = rl[0]; bl[2 * p][1] = rl[1];
            bl[2 * p + 1][0] = rl[2]; bl[2 * p + 1][1] = rl[3];
        }
        #pragma unroll
        for (int term = 0; term < 3; term++) {
            #pragma unroll
            for (int mf = 0; mf < 4; mf++)
                #pragma unroll
                for (int nf = 0; nf < 4; nf++) {
                    const uint32_t* ap = (term == 2) ? al[mf] : ah[mf];
                    const uint32_t* bp = (term == 1) ? bl[nf] : bh[nf];
                    ptx_mma_h(acc[mf][nf], ap, bp);
                }
        }
        if (it + 1 < NIT) {
            uint32_t* d = sm + ((it + 1) & 1) * BUFW;
            stage(d,            fr,      fkq, fa0, sA);
            stage(d,            fr + 64, fkq, fa1, sA);
            stage(d + 2 * MOFF, fr,      fkq, fb0, sB);
            stage(d + 2 * MOFF, fr + 64, fkq, fb1, sB);
            __syncthreads();
        }
    }
}

// epilogue iteration helper (256-thread, warp tile 64x32)
#define EPI_BEGIN \
    const int lane_ = threadIdx.x & 31, wid_ = threadIdx.x >> 5; \
    const int wm_ = wid_ >> 2, wn_ = wid_ & 3, lr_ = lane_ >> 2, lc_ = lane_ & 3; \
    _Pragma("unroll") for (int mf = 0; mf < 4; mf++) \
    _Pragma("unroll") for (int nf = 0; nf < 4; nf++) \
    _Pragma("unroll") for (int hf = 0; hf < 2; hf++) { \
        const int r  = wm_ * 64 + mf * 16 + lr_ + hf * 8; \
        const int cI = wn_ * 32 + nf * 8 + lc_ * 2; \
        const float v0 = acc[mf][nf][hf * 2], v1 = acc[mf][nf][hf * 2 + 1];
#define EPI_END }

// ---------------- mma-based kernels ----------------

// projection + bias + scale; vmode=0: heads layout; vmode=1: vT layout [z][d][t]
__global__ void __launch_bounds__(256, 1) k_proj_mma(
    const float* __restrict__ X, const float* __restrict__ W,
    const float* __restrict__ bias, float* __restrict__ out, int T, float scale,
    int vmode, float sA, float sB, float inv)
{
    extern __shared__ uint32_t sm[];
    float acc[4][4][4] = {};
    const int row0 = blockIdx.y * 128, col0 = blockIdx.x * 128;
    mm_core_h(X + (size_t)row0 * Ee, W + (size_t)col0 * Ee, Ee, Ee, Ee, sA, sB, acc, sm);
    EPI_BEGIN
        const int gr = row0 + r, gc = col0 + cI;
        const int t = gr >> 2, bb = gr & 3;
        const int h = gc >> 6, d = gc & 63;
        const int z = bb * Hh + h;
        const float o0 = (v0 * inv + bias[gc]) * scale;
        const float o1 = (v1 * inv + bias[gc + 1]) * scale;
        if (vmode) {
            out[((size_t)z * 128 + d) * TBq + t]     = o0;
            out[((size_t)z * 128 + d + 1) * TBq + t] = o1;
        } else {
            *(float2*)&out[(((size_t)z) * T + t) * Dd + d] = make_float2(o0, o1);
        }
    EPI_END
}

// QK^T + relative logits.
// mode 0: A=q, B=k, out[t][s]; mode 1: A=k, B=q, out[s][t] (transposed logits)
__global__ void __launch_bounds__(256, 1) k_attn_mma(
    const float* __restrict__ Amat, const float* __restrict__ Bmat,
    const float* __restrict__ allr, float* __restrict__ attn, int T, int mode,
    float sA, float sB, float inv)
{
    extern __shared__ uint32_t sm[];
    const int z = blockIdx.z;
    const int row0 = blockIdx.y * 128, col0 = blockIdx.x * 128;
    const float* A = Amat + (size_t)z * T * Dd + (size_t)row0 * Dd;
    const float* B = Bmat + (size_t)z * T * Dd + (size_t)col0 * Dd;
    float acc[4][4][4] = {};
    mm_core_h(A, B, Dd, Dd, Dd, sA, sB, acc, sm);
    EPI_BEGIN
        const int gr = row0 + r;
        const int gc = col0 + cI;
        float o0, o1;
        if (mode == 0) {
            const float* ar = allr + ((size_t)z * T + gr) * Rr;
            int r0c = gc - gr;     r0c = r0c < -Ll ? -Ll : (r0c > Ll ? Ll : r0c);
            int r1c = gc + 1 - gr; r1c = r1c < -Ll ? -Ll : (r1c > Ll ? Ll : r1c);
            o0 = v0 * inv + ar[r0c + Ll];
            o1 = v1 * inv + ar[r1c + Ll];
        } else {
            int r0c = gr - gc;       r0c = r0c < -Ll ? -Ll : (r0c > Ll ? Ll : r0c);
            int r1c = gr - (gc + 1); r1c = r1c < -Ll ? -Ll : (r1c > Ll ? Ll : r1c);
            o0 = v0 * inv + allr[((size_t)z * T + gc) * Rr + r0c + Ll];
            o1 = v1 * inv + allr[((size_t)z * T + gc + 1) * Rr + r1c + Ll];
        }
        *(float2*)&attn[((size_t)z * T + gr) * T + gc] = make_float2(o0, o1);
    EPI_END
}

// batched NT GEMM: C[z] (+)= A[z/aZd] * B[z/bZd]^T
template<bool ADD>
__global__ void __launch_bounds__(256, 1) k_mmNT(
    const float* __restrict__ Ab, const float* __restrict__ Bb, float* __restrict__ Cb,
    int lda, int ldb, int ldc, int K,
    long long aZs, int aZd, long long bZs, int bZd, long long cZs,
    float sA, float sB, float inv)
{
    extern __shared__ uint32_t sm[];
    const int z = blockIdx.z;
    const int row0 = blockIdx.y * 128, col0 = blockIdx.x * 128;
    const float* A = Ab + (size_t)(z / aZd) * aZs + (size_t)row0 * lda;
    const float* B = Bb + (size_t)(z / bZd) * bZs + (size_t)col0 * ldb;
    float* C = Cb + (size_t)z * cZs;
    float acc[4][4][4] = {};
    mm_core_h(A, B, lda, ldb, K, sA, sB, acc, sm);
    EPI_BEGIN
        float2* p = (float2*)&C[(size_t)(row0 + r) * ldc + col0 + cI];
        float2 v = make_float2(v0 * inv, v1 * inv);
        if (ADD) { float2 o = *p; v.x += o.x; v.y += o.y; }
        *p = v;
    EPI_END
}

// probs @ v via vT (padded to 128 rows; pad rows are zero): columns >= 64 discarded
__global__ void __launch_bounds__(256, 1) k_pv_mma(float sA, float sB, float inv)
{
    extern __shared__ uint32_t sm[];
    const int z = blockIdx.z, bb = z / Hh, h = z % Hh;
    const int row0 = blockIdx.y * 128;
    const float* A = g_attn + (size_t)z * TBq * TBq + (size_t)row0 * TBq;
    const float* B = g_vT   + (size_t)z * 128 * TBq;
    float acc[4][4][4] = {};
    mm_core_h(A, B, TBq, TBq, TBq, sA, sB, acc, sm);
    EPI_BEGIN
        if (cI < 64) {
            const int t = row0 + r, d = cI;
            *(float2*)&g_x2[((size_t)t * NBa + bb) * Ee + h * Dd + d] =
                make_float2(v0 * inv, v1 * inv);
        }
    EPI_END
}

// output projection + bias
__global__ void __launch_bounds__(256, 1) k_final_mma(
    const float* __restrict__ X, const float* __restrict__ Wo,
    const float* __restrict__ bo, float* __restrict__ out,
    float sA, float sB, float inv)
{
    extern __shared__ uint32_t sm[];
    float acc[4][4][4] = {};
    const int row0 = blockIdx.y * 128, col0 = blockIdx.x * 128;
    mm_core_h(X + (size_t)row0 * Ee, Wo + (size_t)col0 * Ee, Ee, Ee, Ee, sA, sB, acc, sm);
    EPI_BEGIN
        const int gr = row0 + r, gc = col0 + cI;
        *(float2*)&out[(size_t)gr * Ee + gc] =
            make_float2(v0 * inv + bo[gc], v1 * inv + bo[gc + 1]);
    EPI_END
}

// ---------------- remaining SIMT kernels ----------------
__global__ void k_allr(const float* __restrict__ q, const float* __restrict__ table,
                       float* __restrict__ allr, int T)
{
    int idx = blockIdx.x * blockDim.x + threadIdx.x;
    if (idx >= NHh * T * Rr) return;
    int r   = idx % Rr;
    int row = idx / Rr;
    const float* qp = q + (size_t)row * Dd;
    const float* tp = table + r * Dd;
    float s = 0.f;
    #pragma unroll
    for (int d = 0; d < Dd; d++) s += qp[d] * tp[d];
    allr[idx] = s;
}

__global__ void k_softmax()
{
    const size_t row = blockIdx.x;
    float4* p = (float4*)(g_attn + row * TBq);
    float4 v = p[threadIdx.x];
    float m = fmaxf(fmaxf(v.x, v.y), fmaxf(v.z, v.w));

    __shared__ float smx[8];
    __shared__ float ssm[8];
    int lane = threadIdx.x & 31, w = threadIdx.x >> 5;
    #pragma unroll
    for (int o = 16; o; o >>= 1) m = fmaxf(m, __shfl_xor_sync(0xffffffffu, m, o));
    if (!lane) smx[w] = m;
    __syncthreads();
    m = smx[0];
    #pragma unroll
    for (int i = 1; i < 8; i++) m = fmaxf(m, smx[i]);

    v.x = expf(v.x - m); v.y = expf(v.y - m);
    v.z = expf(v.z - m); v.w = expf(v.w - m);
    float s = v.x + v.y + v.z + v.w;
    #pragma unroll
    for (int o = 16; o; o >>= 1) s += __shfl_xor_sync(0xffffffffu, s, o);
    if (!lane) ssm[w] = s;
    __syncthreads();
    s = 0.f;
    #pragma unroll
    for (int i = 0; i < 8; i++) s += ssm[i];

    float inv = 1.f / s;
    v.x *= inv; v.y *= inv; v.z *= inv; v.w *= inv;
    p[threadIdx.x] = v;
}

// ---------------- launcher ----------------
extern "C" void kernel_launch(void* const* d_in, const int* in_sizes, int n_in,
                              void* d_out, int out_size)
{
    const float* query_bpe  = (const float*)d_in[0];
    const float* query_word = (const float*)d_in[1];
    const float* mapping    = (const float*)d_in[2];
    const float* Wq_bpe     = (const float*)d_in[3];
    const float* bq_bpe     = (const float*)d_in[4];
    const float* Wk_bpe     = (const float*)d_in[5];
    const float* bk_bpe     = (const float*)d_in[6];
    const float* Wq_word    = (const float*)d_in[7];
    const float* bq_word    = (const float*)d_in[8];
    const float* Wk_word    = (const float*)d_in[9];
    const float* bk_word    = (const float*)d_in[10];
    const float* Wv         = (const float*)d_in[11];
    const float* bv         = (const float*)d_in[12];
    const float* Wo         = (const float*)d_in[13];
    const float* bo         = (const float*)d_in[14];
    const float* rel_keys   = (const float*)d_in[15];
    float* out = (float*)d_out;

    float *q_bpe, *k_bpe, *vT, *q_w, *k_w, *attn, *awT, *tmp, *arb, *arw, *x2;
    cudaGetSymbolAddress((void**)&q_bpe, g_q_bpe);
    cudaGetSymbolAddress((void**)&k_bpe, g_k_bpe);
    cudaGetSymbolAddress((void**)&vT,    g_vT);
    cudaGetSymbolAddress((void**)&q_w,   g_q_w);
    cudaGetSymbolAddress((void**)&k_w,   g_k_w);
    cudaGetSymbolAddress((void**)&attn,  g_attn);
    cudaGetSymbolAddress((void**)&awT,   g_awT);
    cudaGetSymbolAddress((void**)&tmp,   g_tmp);
    cudaGetSymbolAddress((void**)&arb,   g_arb);
    cudaGetSymbolAddress((void**)&arw,   g_arw);
    cudaGetSymbolAddress((void**)&x2,    g_x2);

    cudaFuncSetAttribute(k_proj_mma,    cudaFuncAttributeMaxDynamicSharedMemorySize, MM_SMEM);
    cudaFuncSetAttribute(k_attn_mma,    cudaFuncAttributeMaxDynamicSharedMemorySize, MM_SMEM);
    cudaFuncSetAttribute(k_mmNT<false>, cudaFuncAttributeMaxDynamicSharedMemorySize, MM_SMEM);
    cudaFuncSetAttribute(k_mmNT<true>,  cudaFuncAttributeMaxDynamicSharedMemorySize, MM_SMEM);
    cudaFuncSetAttribute(k_pv_mma,      cudaFuncAttributeMaxDynamicSharedMemorySize, MM_SMEM);
    cudaFuncSetAttribute(k_final_mma,   cudaFuncAttributeMaxDynamicSharedMemorySize, MM_SMEM);

    // per-GEMM fp16 prescales (powers of 2, generous overflow margins)
    const float sX = 64.f,    sW = 2048.f,  iXW = 1.f / (sX * sW);     // projections
    const float sQ = 1024.f,  sK = 128.f,   iQK = 1.f / (sQ * sK);     // attn logits
    const float sM = 64.f,    sAw = 128.f,  iMA = 1.f / (sM * sAw);    // tmp = M @ aw^T
    const float sTm = 16.f,   sM2 = 64.f,   iTM = 1.f / (sTm * sM2);   // fuse = tmp @ M^T
    const float sP = 256.f,   sV = 128.f,   iPV = 1.f / (sP * sV);     // probs @ v
    const float sX2 = 128.f,  sWo = 2048.f, iXO = 1.f / (sX2 * sWo);   // final

    // projections (M = T*NB rows); v written transposed+padded
    k_proj_mma<<<dim3(8, 32), 256, MM_SMEM>>>(query_bpe,  Wq_bpe,  bq_bpe,  q_bpe, TBq, SCALE, 0, sX, sW, iXW);
    k_proj_mma<<<dim3(8, 32), 256, MM_SMEM>>>(query_bpe,  Wk_bpe,  bk_bpe,  k_bpe, TBq, 1.0f,  0, sX, sW, iXW);
    k_proj_mma<<<dim3(8, 32), 256, MM_SMEM>>>(query_bpe,  Wv,      bv,      vT,    TBq, 1.0f,  1, sX, sW, iXW);
    k_proj_mma<<<dim3(8, 16), 256, MM_SMEM>>>(query_word, Wq_word, bq_word, q_w,   TWq, SCALE, 0, sX, sW, iXW);
    k_proj_mma<<<dim3(8, 16), 256, MM_SMEM>>>(query_word, Wk_word, bk_word, k_w,   TWq, 1.0f,  0, sX, sW, iXW);

    // relative logit tables
    k_allr<<<(NHh * TBq * Rr + 255) / 256, 256>>>(q_bpe, rel_keys, arb, TBq);
    k_allr<<<(NHh * TWq * Rr + 255) / 256, 256>>>(q_w,   rel_keys, arw, TWq);

    // content + relative logits; word stream computed directly transposed
    k_attn_mma<<<dim3(8, 8, NHh), 256, MM_SMEM>>>(q_bpe, k_bpe, arb, attn, TBq, 0, sQ, sK, iQK);
    k_attn_mma<<<dim3(4, 4, NHh), 256, MM_SMEM>>>(k_w,   q_w,   arw, awT,  TWq, 1, sK, sQ, iQK);

    // fusion chain on tensor cores
    k_mmNT<false><<<dim3(TWq / 128, TBq / 128, NHh), 256, MM_SMEM>>>(
        mapping, awT, tmp, TWq, TWq, TWq, TWq,
        (long long)TBq * TWq, Hh, (long long)TWq * TWq, 1, (long long)TBq * TWq,
        sM, sAw, iMA);
    k_mmNT<true><<<dim3(TBq / 128, TBq / 128, NHh), 256, MM_SMEM>>>(
        tmp, mapping, attn, TWq, TWq, TBq, TWq,
        (long long)TBq * TWq, 1, (long long)TBq * TWq, Hh, (long long)TBq * TBq,
        sTm, sM2, iTM);

    // softmax rows
    k_softmax<<<NHh * TBq, 256>>>();

    // probs @ v on tensor cores
    k_pv_mma<<<dim3(1, 8, NHh), 256, MM_SMEM>>>(sP, sV, iPV);

    // output projection
    k_final_mma<<<dim3(8, 32), 256, MM_SMEM>>>(x2, Wo, bo, out, sX2, sWo, iXO);
}